// round 5
// baseline (speedup 1.0000x reference)
#include <cuda_runtime.h>
#include <cstdint>

// Problem dims: C=64, S=256, T=500, N=2000
// Output layout (concatenated, float32):
//   log_obs    [T,N]      at offset 0            (1,000,000)
//   log_obs_   [T,C,N]    at offset 1,000,000    (64,000,000)
//   log_hidden [T,C,S]    at offset 65,000,000   (8,192,000)

static __device__ float g_Ppow[64 * 256 * 256];   // g_Ppow[i] = P^(i+1), i=0..63
static __device__ float g_Ppt[64 * 256 * 256];    // transposed powers
static __device__ float g_Q[8 * 256 * 256];       // Q^k = P^(64k), slots 2..7
static __device__ float g_p[500 * 64 * 256];      // probabilities p_t  [T][C][S]
static __device__ float g_E[256 * 2000];          // E, then Ee = E/colmax in place
static __device__ float g_Et[2048 * 256];         // Ee transposed [N_pad][S], zero padded
static __device__ float g_bmaxE[2048];            // log(colmax of E)
static __device__ float g_w[500 * 64];            // softmax chain weights
static __device__ float g_wp[500 * 256];          // wp[t,s] = sum_c w[t,c] p_t[c,s]

// ================= block reductions =================
__device__ __forceinline__ float bredMax(float v) {
    __shared__ float sm[8];
    unsigned nw = blockDim.x >> 5;
#pragma unroll
    for (int o = 16; o; o >>= 1) v = fmaxf(v, __shfl_xor_sync(0xffffffffu, v, o));
    if ((threadIdx.x & 31) == 0) sm[threadIdx.x >> 5] = v;
    __syncthreads();
    if (threadIdx.x < 32) {
        v = (threadIdx.x < nw) ? sm[threadIdx.x] : -3.402823e38f;
#pragma unroll
        for (int o = 4; o; o >>= 1) v = fmaxf(v, __shfl_xor_sync(0xffffffffu, v, o));
        if (threadIdx.x == 0) sm[0] = v;
    }
    __syncthreads();
    v = sm[0];
    __syncthreads();
    return v;
}
__device__ __forceinline__ float bredSum(float v) {
    __shared__ float sm[8];
    unsigned nw = blockDim.x >> 5;
#pragma unroll
    for (int o = 16; o; o >>= 1) v += __shfl_xor_sync(0xffffffffu, v, o);
    if ((threadIdx.x & 31) == 0) sm[threadIdx.x >> 5] = v;
    __syncthreads();
    if (threadIdx.x < 32) {
        v = (threadIdx.x < nw) ? sm[threadIdx.x] : 0.f;
#pragma unroll
        for (int o = 4; o; o >>= 1) v += __shfl_xor_sync(0xffffffffu, v, o);
        if (threadIdx.x == 0) sm[0] = v;
    }
    __syncthreads();
    v = sm[0];
    __syncthreads();
    return v;
}

// ================= preprocessing =================
__global__ void k_softmax_P(const float* __restrict__ x) {
    int r = blockIdx.x;
    float v = x[r * 256 + threadIdx.x];
    float m = bredMax(v);
    float e = __expf(v - m);
    float Z = bredSum(e);
    float p = e / Z;
    g_Ppow[r * 256 + threadIdx.x] = p;
    g_Ppt[threadIdx.x * 256 + r] = p;
}
__global__ void k_softmax_p0(const float* __restrict__ x, float* __restrict__ hid) {
    int r = blockIdx.x;
    float v = x[r * 256 + threadIdx.x];
    float m = bredMax(v);
    float e = __expf(v - m);
    float Z = bredSum(e);
    g_p[r * 256 + threadIdx.x] = e / Z;
    hid[r * 256 + threadIdx.x] = (v - m) - __logf(Z);
}
__global__ void k_softmax_w(const float* __restrict__ x) {
    int r = blockIdx.x;
    float v = x[r * 64 + threadIdx.x];
    float m = bredMax(v);
    float e = __expf(v - m);
    float Z = bredSum(e);
    g_w[r * 64 + threadIdx.x] = e / Z;
}
__global__ void k_Erow(const float* __restrict__ x, const float* __restrict__ mask) {
    int s = blockIdx.x;
    const float* xr = x + (size_t)s * 2000;
    const float* mr = mask + (size_t)s * 2000;
    float* Er = g_E + (size_t)s * 2000;
    float m = -3.402823e38f;
    for (int n = threadIdx.x; n < 2000; n += 256)
        if (mr[n] > 0.f) m = fmaxf(m, xr[n]);
    m = bredMax(m);
    float sloc = 0.f;
    for (int n = threadIdx.x; n < 2000; n += 256) {
        float e = (mr[n] > 0.f) ? __expf(xr[n] - m) * mr[n] : 0.f;
        Er[n] = e;
        sloc += e;
    }
    float Z = bredSum(sloc);
    float inv = 1.f / Z;
    for (int n = threadIdx.x; n < 2000; n += 256) Er[n] *= inv;
}
// colmax + rescale + transpose fused
__global__ void k_Ecol() {
    int n = blockIdx.x * 256 + threadIdx.x;
    if (n >= 2000) return;
    float m = 0.f;
    for (int s = 0; s < 256; s++) m = fmaxf(m, g_E[(size_t)s * 2000 + n]);
    g_bmaxE[n] = __logf(m);
    float inv = 1.f / m;
    for (int s = 0; s < 256; s++) {
        float v = g_E[(size_t)s * 2000 + n] * inv;
        g_E[(size_t)s * 2000 + n] = v;
        g_Et[(size_t)n * 256 + s] = v;
    }
}

// ================= SIMT 64x64xK=256 GEMM core (macro body) =================
#define GEMM_BODY(Aexpr, Bexpr)                                                       \
    __shared__ float As[64][68];                                                      \
    __shared__ float Bs[64][68];                                                      \
    const int u = threadIdx.x;                                                        \
    const int tx = u & 15, ty = u >> 4;                                               \
    float acc[4][4];                                                                  \
    _Pragma("unroll") for (int i = 0; i < 4; i++)                                     \
        _Pragma("unroll") for (int j = 0; j < 4; j++) acc[i][j] = 0.f;                \
    for (int k0 = 0; k0 < 256; k0 += 64) {                                            \
        _Pragma("unroll") for (int q = 0; q < 4; q++) {                               \
            int f = q * 256 + u;                                                      \
            int row = f >> 4, kq = (f & 15) << 2;                                     \
            *(float4*)&As[row][kq] = *(const float4*)&(Aexpr);                        \
            *(float4*)&Bs[row][kq] = *(const float4*)&(Bexpr);                        \
        }                                                                             \
        __syncthreads();                                                              \
        _Pragma("unroll") for (int k2 = 0; k2 < 64; k2++) {                           \
            float a0 = As[ty * 4 + 0][k2], a1 = As[ty * 4 + 1][k2];                   \
            float a2 = As[ty * 4 + 2][k2], a3 = As[ty * 4 + 3][k2];                   \
            float4 b = *(const float4*)&Bs[k2][tx * 4];                               \
            acc[0][0] += a0 * b.x; acc[0][1] += a0 * b.y; acc[0][2] += a0 * b.z; acc[0][3] += a0 * b.w; \
            acc[1][0] += a1 * b.x; acc[1][1] += a1 * b.y; acc[1][2] += a1 * b.z; acc[1][3] += a1 * b.w; \
            acc[2][0] += a2 * b.x; acc[2][1] += a2 * b.y; acc[2][2] += a2 * b.z; acc[2][3] += a2 * b.w; \
            acc[3][0] += a3 * b.x; acc[3][1] += a3 * b.y; acc[3][2] += a3 * b.z; acc[3][3] += a3 * b.w; \
        }                                                                             \
        __syncthreads();                                                              \
    }

// Batched power: Ppow[dst+z] = Ppow[src+z] @ Ppow[pw]; also stores transpose.
__global__ __launch_bounds__(256) void k_pmul(int dst, int src, int pw) {
    const int z = blockIdx.z;
    const float* A = g_Ppow + (size_t)(src + z) * 65536;
    const float* B = g_Ppow + (size_t)pw * 65536;
    float* Cm = g_Ppow + (size_t)(dst + z) * 65536;
    float* Ct = g_Ppt + (size_t)(dst + z) * 65536;
    const int r0 = blockIdx.y * 64, c0 = blockIdx.x * 64;
    GEMM_BODY(A[(size_t)(r0 + row) * 256 + k0 + kq],
              B[(size_t)(k0 + row) * 256 + c0 + kq])
#pragma unroll
    for (int i = 0; i < 4; i++) {
        *(float4*)&Cm[(size_t)(r0 + ty * 4 + i) * 256 + c0 + tx * 4] =
            make_float4(acc[i][0], acc[i][1], acc[i][2], acc[i][3]);
#pragma unroll
        for (int j = 0; j < 4; j++)
            Ct[(size_t)(c0 + tx * 4 + j) * 256 + r0 + ty * 4 + i] = acc[i][j];
    }
}

__device__ __forceinline__ const float* Qptr(int k) {
    return (k == 1) ? (g_Ppow + (size_t)63 * 65536) : (g_Q + (size_t)k * 65536);
}

// Batched Q powers: Q^(dst0+z) = Q^(src0+z) @ Q^pw  (fp32)
__global__ __launch_bounds__(256) void k_qmul(int dst0, int src0, int pw) {
    const int z = blockIdx.z;
    const float* A = Qptr(src0 + z);
    const float* B = Qptr(pw);
    float* Cm = g_Q + (size_t)(dst0 + z) * 65536;
    const int r0 = blockIdx.y * 64, c0 = blockIdx.x * 64;
    GEMM_BODY(A[(size_t)(r0 + row) * 256 + k0 + kq],
              B[(size_t)(k0 + row) * 256 + c0 + kq])
#pragma unroll
    for (int i = 0; i < 4; i++)
        *(float4*)&Cm[(size_t)(r0 + ty * 4 + i) * 256 + c0 + tx * 4] =
            make_float4(acc[i][0], acc[i][1], acc[i][2], acc[i][3]);
}

// All backbones in one launch: p[64k] = p0 @ Q^k, k = blockIdx.y+1 (fp32)
__global__ __launch_bounds__(256) void k_bb_all() {
    const int k = blockIdx.y + 1;
    const float* A = g_p;
    const float* B = Qptr(k);
    float* Cm = g_p + (size_t)(64 * k) * 16384;
    const int c0 = blockIdx.x * 64;
    GEMM_BODY(A[(size_t)row * 256 + k0 + kq],
              B[(size_t)(k0 + row) * 256 + c0 + kq])
#pragma unroll
    for (int i = 0; i < 4; i++)
        *(float4*)&Cm[(size_t)(ty * 4 + i) * 256 + c0 + tx * 4] =
            make_float4(acc[i][0], acc[i][1], acc[i][2], acc[i][3]);
}

// ================= tf32 mma.sync =================
__device__ __forceinline__ void mma_tf32(float* c, const uint32_t* a, const uint32_t* b) {
    asm volatile(
        "mma.sync.aligned.m16n8k8.row.col.f32.tf32.tf32.f32 "
        "{%0,%1,%2,%3}, {%4,%5,%6,%7}, {%8,%9}, {%0,%1,%2,%3};"
        : "+f"(c[0]), "+f"(c[1]), "+f"(c[2]), "+f"(c[3])
        : "r"(a[0]), "r"(a[1]), "r"(a[2]), "r"(a[3]), "r"(b[0]), "r"(b[1]));
}

// Fill via MMA: p_t[64 x 128-tile] = p_base[64,256] @ P^i, hid = log(p_t)
// grid: (2 N-tiles, 499 t), 256 threads = 8 warps (2 M x 4 N)
__global__ __launch_bounds__(256) void k_fill_mma(float* __restrict__ hid) {
    __shared__ float sA[64][36];
    __shared__ float sB[128][36];
    const int u = threadIdx.x;
    const int lane = u & 31;
    const int w = u >> 5;
    const int wm = w & 1;
    const int wn = w >> 1;
    const int t = blockIdx.y + 1;
    const int base = ((t - 1) >> 6) << 6;
    const int i = t - base;
    const float* A = g_p + (size_t)base * 16384;
    const float* Bt = g_Ppt + (size_t)(i - 1) * 65536;
    const int c0 = blockIdx.x * 128;

    float acc[2][4][4];
#pragma unroll
    for (int mt = 0; mt < 2; mt++)
#pragma unroll
        for (int nt = 0; nt < 4; nt++)
#pragma unroll
            for (int r = 0; r < 4; r++) acc[mt][nt][r] = 0.f;

    const int lr = lane >> 2;
    const int lc = lane & 3;

    for (int ch = 0; ch < 8; ch++) {
        const int k0 = ch * 32;
#pragma unroll
        for (int q = 0; q < 2; q++) {
            int f = q * 256 + u;
            int row = f >> 3, c4 = (f & 7) << 2;
            *(float4*)&sA[row][c4] = *(const float4*)&A[(size_t)row * 256 + k0 + c4];
        }
#pragma unroll
        for (int q = 0; q < 4; q++) {
            int f = q * 256 + u;
            int row = f >> 3, c4 = (f & 7) << 2;
            *(float4*)&sB[row][c4] = *(const float4*)&Bt[(size_t)(c0 + row) * 256 + k0 + c4];
        }
        __syncthreads();
#pragma unroll
        for (int k8 = 0; k8 < 4; k8++) {
            const int kb = k8 * 8;
            uint32_t bfr[4][2];
#pragma unroll
            for (int nt = 0; nt < 4; nt++) {
                const int nrow = wn * 32 + nt * 8 + lr;
                bfr[nt][0] = __float_as_uint(sB[nrow][kb + lc]);
                bfr[nt][1] = __float_as_uint(sB[nrow][kb + lc + 4]);
            }
#pragma unroll
            for (int mt = 0; mt < 2; mt++) {
                const int arow = wm * 32 + mt * 16 + lr;
                uint32_t afr[4];
                afr[0] = __float_as_uint(sA[arow][kb + lc]);
                afr[1] = __float_as_uint(sA[arow + 8][kb + lc]);
                afr[2] = __float_as_uint(sA[arow][kb + lc + 4]);
                afr[3] = __float_as_uint(sA[arow + 8][kb + lc + 4]);
#pragma unroll
                for (int nt = 0; nt < 4; nt++) mma_tf32(acc[mt][nt], afr, bfr[nt]);
            }
        }
        __syncthreads();
    }

    float* pout = g_p + (size_t)t * 16384;
    float* hout = hid + (size_t)t * 16384;
#pragma unroll
    for (int mt = 0; mt < 2; mt++) {
        const int row = wm * 32 + mt * 16 + lr;
#pragma unroll
        for (int nt = 0; nt < 4; nt++) {
            const int col = c0 + wn * 32 + nt * 8 + 2 * lc;
            float2 v0 = make_float2(acc[mt][nt][0], acc[mt][nt][1]);
            float2 v1 = make_float2(acc[mt][nt][2], acc[mt][nt][3]);
            *(float2*)&pout[(size_t)row * 256 + col] = v0;
            *(float2*)&pout[(size_t)(row + 8) * 256 + col] = v1;
            *(float2*)&hout[(size_t)row * 256 + col] = make_float2(__logf(v0.x), __logf(v0.y));
            *(float2*)&hout[(size_t)(row + 8) * 256 + col] = make_float2(__logf(v1.x), __logf(v1.y));
        }
    }
}

// wp[t,s] = sum_c w[t,c] * p_t[c,s]
__global__ void k_wsum() {
    int t = blockIdx.x, s = threadIdx.x;
    const float* p = g_p + (size_t)t * 16384;
    float a = 0.f;
#pragma unroll 8
    for (int c = 0; c < 64; c++) a += g_w[t * 64 + c] * p[c * 256 + s];
    g_wp[(size_t)t * 256 + s] = a;
}

// ================= emission GEMM: pipelined tf32 MMA =================
// CTA 128 rows x 256 cols, 8 warps (2M x 4N), warp tile 64x64.
// Dynamic SMEM: A[2][128][36], B[2][256][36], BM[256]
#define EMIS_SMEM_FLOATS (2 * 128 * 36 + 2 * 256 * 36 + 256)

__global__ __launch_bounds__(256) void k_emis_mma(float* __restrict__ out) {
    extern __shared__ float smdy[];
    float* sAb[2] = {smdy, smdy + 128 * 36};
    float* sBb[2] = {smdy + 2 * 128 * 36, smdy + 2 * 128 * 36 + 256 * 36};
    float* sBM = smdy + 2 * 128 * 36 + 2 * 256 * 36;

    const int u = threadIdx.x;
    const int lane = u & 31;
    const int w = u >> 5;
    const int wm = w & 1;    // 2 M-groups of 64 rows
    const int wn = w >> 1;   // 4 N-groups of 64 cols
    const int n0 = blockIdx.x * 256;
    const int r0 = blockIdx.y * 128;

    sBM[u] = g_bmaxE[n0 + u];

#define EMIS_PREFETCH(ch, st)                                                          \
    {                                                                                  \
        const int k0_ = (ch) * 32;                                                     \
        _Pragma("unroll") for (int q = 0; q < 4; q++) {                                \
            int f = q * 256 + u;                                                       \
            int row = f >> 3, c4 = (f & 7) << 2;                                       \
            uint32_t dst = (uint32_t)__cvta_generic_to_shared(&sAb[st][row * 36 + c4]);\
            asm volatile("cp.async.cg.shared.global [%0], [%1], 16;" ::                \
                         "r"(dst), "l"(&g_p[(size_t)(r0 + row) * 256 + k0_ + c4]));    \
        }                                                                              \
        _Pragma("unroll") for (int q = 0; q < 8; q++) {                                \
            int f = q * 256 + u;                                                       \
            int row = f >> 3, c4 = (f & 7) << 2;                                       \
            uint32_t dst = (uint32_t)__cvta_generic_to_shared(&sBb[st][row * 36 + c4]);\
            asm volatile("cp.async.cg.shared.global [%0], [%1], 16;" ::                \
                         "r"(dst), "l"(&g_Et[(size_t)(n0 + row) * 256 + k0_ + c4]));   \
        }                                                                              \
        asm volatile("cp.async.commit_group;");                                        \
    }

    float acc[4][8][4];
#pragma unroll
    for (int mt = 0; mt < 4; mt++)
#pragma unroll
        for (int nt = 0; nt < 8; nt++)
#pragma unroll
            for (int r = 0; r < 4; r++) acc[mt][nt][r] = 0.f;

    const int lr = lane >> 2;
    const int lc = lane & 3;

    EMIS_PREFETCH(0, 0)

    for (int ch = 0; ch < 8; ch++) {
        if (ch < 7) {
            EMIS_PREFETCH(ch + 1, (ch + 1) & 1)
            asm volatile("cp.async.wait_group 1;");
        } else {
            asm volatile("cp.async.wait_group 0;");
        }
        __syncthreads();
        const float* A = sAb[ch & 1];
        const float* B = sBb[ch & 1];
#pragma unroll
        for (int k8 = 0; k8 < 4; k8++) {
            const int kb = k8 * 8;
            uint32_t bfr[8][2];
#pragma unroll
            for (int nt = 0; nt < 8; nt++) {
                const int nrow = wn * 64 + nt * 8 + lr;
                bfr[nt][0] = __float_as_uint(B[nrow * 36 + kb + lc]);
                bfr[nt][1] = __float_as_uint(B[nrow * 36 + kb + lc + 4]);
            }
#pragma unroll
            for (int mt = 0; mt < 4; mt++) {
                const int arow = wm * 64 + mt * 16 + lr;
                uint32_t afr[4];
                afr[0] = __float_as_uint(A[arow * 36 + kb + lc]);
                afr[1] = __float_as_uint(A[(arow + 8) * 36 + kb + lc]);
                afr[2] = __float_as_uint(A[arow * 36 + kb + lc + 4]);
                afr[3] = __float_as_uint(A[(arow + 8) * 36 + kb + lc + 4]);
#pragma unroll
                for (int nt = 0; nt < 8; nt++) mma_tf32(acc[mt][nt], afr, bfr[nt]);
            }
        }
        __syncthreads();
    }
#undef EMIS_PREFETCH

    float* obsp = out + 1000000u;
#pragma unroll
    for (int mt = 0; mt < 4; mt++) {
        const int row = r0 + wm * 64 + mt * 16 + lr;
#pragma unroll
        for (int nt = 0; nt < 8; nt++) {
            const int col = wn * 64 + nt * 8 + 2 * lc;
            const int n = n0 + col;
            if (n < 2000) {
                float2 v0, v1;
                v0.x = __logf(acc[mt][nt][0]) + sBM[col];
                v0.y = __logf(acc[mt][nt][1]) + sBM[col + 1];
                v1.x = __logf(acc[mt][nt][2]) + sBM[col];
                v1.y = __logf(acc[mt][nt][3]) + sBM[col + 1];
                *(float2*)&obsp[(size_t)row * 2000 + n] = v0;
                *(float2*)&obsp[(size_t)(row + 8) * 2000 + n] = v1;
            }
        }
    }
}

// log_obs[t,n] = log( sum_s wp[t,s]*Ee[s,n] ) + bm[n]
__global__ __launch_bounds__(256) void k_obs(float* __restrict__ out) {
    __shared__ float wsm[8 * 256];
    const int t0 = blockIdx.y * 8;
    const int n = blockIdx.x * 256 + threadIdx.x;
#pragma unroll
    for (int j = 0; j < 8; j++)
        wsm[j * 256 + threadIdx.x] =
            (t0 + j < 500) ? g_wp[(size_t)(t0 + j) * 256 + threadIdx.x] : 0.f;
    __syncthreads();
    float acc[8];
#pragma unroll
    for (int j = 0; j < 8; j++) acc[j] = 0.f;
    for (int s = 0; s < 256; s++) {
        float e = (n < 2000) ? g_E[(size_t)s * 2000 + n] : 0.f;
#pragma unroll
        for (int j = 0; j < 8; j++) acc[j] += wsm[j * 256 + s] * e;
    }
    if (n < 2000) {
        float bm = g_bmaxE[n];
#pragma unroll
        for (int j = 0; j < 8; j++)
            if (t0 + j < 500) out[(size_t)(t0 + j) * 2000 + n] = __logf(acc[j]) + bm;
    }
}

// ================= launch =================
extern "C" void kernel_launch(void* const* d_in, const int* in_sizes, int n_in,
                              void* d_out, int out_size) {
    const float* usi = (const float*)d_in[0];  // [64,256]
    const float* ucw = (const float*)d_in[1];  // [500,64]
    const float* uem = (const float*)d_in[2];  // [256,2000]
    const float* utm = (const float*)d_in[3];  // [256,256]
    const float* msk = (const float*)d_in[4];  // [256,2000]
    float* out = (float*)d_out;
    float* hid = out + 65000000u;

    const int emis_smem = EMIS_SMEM_FLOATS * 4;
    cudaFuncSetAttribute(k_emis_mma, cudaFuncAttributeMaxDynamicSharedMemorySize, emis_smem);

    k_softmax_P<<<256, 256>>>(utm);
    k_softmax_p0<<<64, 256>>>(usi, hid);
    k_softmax_w<<<500, 64>>>(ucw);
    k_Erow<<<256, 256>>>(uem, msk);
    k_Ecol<<<8, 256>>>();

    // P^1..P^64 by batched doubling (fp32, also stores transposes)
    k_pmul<<<dim3(4, 4, 1), 256>>>(1, 0, 0);
    k_pmul<<<dim3(4, 4, 2), 256>>>(2, 0, 1);
    k_pmul<<<dim3(4, 4, 4), 256>>>(4, 0, 3);
    k_pmul<<<dim3(4, 4, 8), 256>>>(8, 0, 7);
    k_pmul<<<dim3(4, 4, 16), 256>>>(16, 0, 15);
    k_pmul<<<dim3(4, 4, 32), 256>>>(32, 0, 31);

    // Q = P^64; Q^2..Q^7 via batched doubling (fp32)
    k_qmul<<<dim3(4, 4, 1), 256>>>(2, 1, 1);  // Q^2
    k_qmul<<<dim3(4, 4, 2), 256>>>(3, 1, 2);  // Q^3, Q^4
    k_qmul<<<dim3(4, 4, 3), 256>>>(5, 1, 4);  // Q^5, Q^6, Q^7

    // all backbones p[64k] = p0 @ Q^k in one launch
    k_bb_all<<<dim3(4, 7), 256>>>();

    // all t = 1..499 via tf32 MMA (writes p and log_hidden)
    k_fill_mma<<<dim3(2, 499), 256>>>(hid);

    k_wsum<<<500, 256>>>();
    k_emis_mma<<<dim3(8, 250), 256, emis_smem>>>(out);
    k_obs<<<dim3(8, 63), 256>>>(out);
}

// round 6
// speedup vs baseline: 1.0575x; 1.0575x over previous
#include <cuda_runtime.h>
#include <cstdint>

// Problem dims: C=64, S=256, T=500, N=2000
// Output layout (concatenated, float32):
//   log_obs    [T,N]      at offset 0            (1,000,000)
//   log_obs_   [T,C,N]    at offset 1,000,000    (64,000,000)
//   log_hidden [T,C,S]    at offset 65,000,000   (8,192,000)

static __device__ float g_Ppow[64 * 256 * 256];   // g_Ppow[i] = P^(i+1), i=0..63
static __device__ float g_Ppt[64 * 256 * 256];    // transposed powers
static __device__ float g_Q[8 * 256 * 256];       // Q^k = P^(64k), slots 2..7
static __device__ float g_p[500 * 64 * 256];      // probabilities p_t  [T][C][S]
static __device__ float g_E[256 * 2000];          // E, then Ee = E/colmax in place
static __device__ float g_Et[2048 * 256];         // Ee transposed [N_pad][S], zero padded
static __device__ float g_bmaxE[2048];            // log(colmax of E)
static __device__ float g_w[500 * 64];            // softmax chain weights
static __device__ float g_wp[500 * 256];          // wp[t,s] = sum_c w[t,c] p_t[c,s]

// ================= block reductions =================
__device__ __forceinline__ float bredMax(float v) {
    __shared__ float sm[8];
    unsigned nw = blockDim.x >> 5;
#pragma unroll
    for (int o = 16; o; o >>= 1) v = fmaxf(v, __shfl_xor_sync(0xffffffffu, v, o));
    if ((threadIdx.x & 31) == 0) sm[threadIdx.x >> 5] = v;
    __syncthreads();
    if (threadIdx.x < 32) {
        v = (threadIdx.x < nw) ? sm[threadIdx.x] : -3.402823e38f;
#pragma unroll
        for (int o = 4; o; o >>= 1) v = fmaxf(v, __shfl_xor_sync(0xffffffffu, v, o));
        if (threadIdx.x == 0) sm[0] = v;
    }
    __syncthreads();
    v = sm[0];
    __syncthreads();
    return v;
}
__device__ __forceinline__ float bredSum(float v) {
    __shared__ float sm[8];
    unsigned nw = blockDim.x >> 5;
#pragma unroll
    for (int o = 16; o; o >>= 1) v += __shfl_xor_sync(0xffffffffu, v, o);
    if ((threadIdx.x & 31) == 0) sm[threadIdx.x >> 5] = v;
    __syncthreads();
    if (threadIdx.x < 32) {
        v = (threadIdx.x < nw) ? sm[threadIdx.x] : 0.f;
#pragma unroll
        for (int o = 4; o; o >>= 1) v += __shfl_xor_sync(0xffffffffu, v, o);
        if (threadIdx.x == 0) sm[0] = v;
    }
    __syncthreads();
    v = sm[0];
    __syncthreads();
    return v;
}

// ================= preprocessing =================
__global__ void k_softmax_P(const float* __restrict__ x) {
    int r = blockIdx.x;
    float v = x[r * 256 + threadIdx.x];
    float m = bredMax(v);
    float e = __expf(v - m);
    float Z = bredSum(e);
    float p = e / Z;
    g_Ppow[r * 256 + threadIdx.x] = p;
    g_Ppt[threadIdx.x * 256 + r] = p;
}
__global__ void k_softmax_p0(const float* __restrict__ x, float* __restrict__ hid) {
    int r = blockIdx.x;
    float v = x[r * 256 + threadIdx.x];
    float m = bredMax(v);
    float e = __expf(v - m);
    float Z = bredSum(e);
    g_p[r * 256 + threadIdx.x] = e / Z;
    hid[r * 256 + threadIdx.x] = (v - m) - __logf(Z);
}
__global__ void k_softmax_w(const float* __restrict__ x) {
    int r = blockIdx.x;
    float v = x[r * 64 + threadIdx.x];
    float m = bredMax(v);
    float e = __expf(v - m);
    float Z = bredSum(e);
    g_w[r * 64 + threadIdx.x] = e / Z;
}
__global__ void k_Erow(const float* __restrict__ x, const float* __restrict__ mask) {
    int s = blockIdx.x;
    const float* xr = x + (size_t)s * 2000;
    const float* mr = mask + (size_t)s * 2000;
    float* Er = g_E + (size_t)s * 2000;
    float m = -3.402823e38f;
    for (int n = threadIdx.x; n < 2000; n += 256)
        if (mr[n] > 0.f) m = fmaxf(m, xr[n]);
    m = bredMax(m);
    float sloc = 0.f;
    for (int n = threadIdx.x; n < 2000; n += 256) {
        float e = (mr[n] > 0.f) ? __expf(xr[n] - m) * mr[n] : 0.f;
        Er[n] = e;
        sloc += e;
    }
    float Z = bredSum(sloc);
    float inv = 1.f / Z;
    for (int n = threadIdx.x; n < 2000; n += 256) Er[n] *= inv;
}
// colmax + rescale + transpose fused
__global__ void k_Ecol() {
    int n = blockIdx.x * 256 + threadIdx.x;
    if (n >= 2000) return;
    float m = 0.f;
    for (int s = 0; s < 256; s++) m = fmaxf(m, g_E[(size_t)s * 2000 + n]);
    g_bmaxE[n] = __logf(m);
    float inv = 1.f / m;
    for (int s = 0; s < 256; s++) {
        float v = g_E[(size_t)s * 2000 + n] * inv;
        g_E[(size_t)s * 2000 + n] = v;
        g_Et[(size_t)n * 256 + s] = v;
    }
}

// ================= SIMT 64x64xK=256 GEMM core (macro body) =================
#define GEMM_BODY(Aexpr, Bexpr)                                                       \
    __shared__ float As[64][68];                                                      \
    __shared__ float Bs[64][68];                                                      \
    const int u = threadIdx.x;                                                        \
    const int tx = u & 15, ty = u >> 4;                                               \
    float acc[4][4];                                                                  \
    _Pragma("unroll") for (int i = 0; i < 4; i++)                                     \
        _Pragma("unroll") for (int j = 0; j < 4; j++) acc[i][j] = 0.f;                \
    for (int k0 = 0; k0 < 256; k0 += 64) {                                            \
        _Pragma("unroll") for (int q = 0; q < 4; q++) {                               \
            int f = q * 256 + u;                                                      \
            int row = f >> 4, kq = (f & 15) << 2;                                     \
            *(float4*)&As[row][kq] = *(const float4*)&(Aexpr);                        \
            *(float4*)&Bs[row][kq] = *(const float4*)&(Bexpr);                        \
        }                                                                             \
        __syncthreads();                                                              \
        _Pragma("unroll") for (int k2 = 0; k2 < 64; k2++) {                           \
            float a0 = As[ty * 4 + 0][k2], a1 = As[ty * 4 + 1][k2];                   \
            float a2 = As[ty * 4 + 2][k2], a3 = As[ty * 4 + 3][k2];                   \
            float4 b = *(const float4*)&Bs[k2][tx * 4];                               \
            acc[0][0] += a0 * b.x; acc[0][1] += a0 * b.y; acc[0][2] += a0 * b.z; acc[0][3] += a0 * b.w; \
            acc[1][0] += a1 * b.x; acc[1][1] += a1 * b.y; acc[1][2] += a1 * b.z; acc[1][3] += a1 * b.w; \
            acc[2][0] += a2 * b.x; acc[2][1] += a2 * b.y; acc[2][2] += a2 * b.z; acc[2][3] += a2 * b.w; \
            acc[3][0] += a3 * b.x; acc[3][1] += a3 * b.y; acc[3][2] += a3 * b.z; acc[3][3] += a3 * b.w; \
        }                                                                             \
        __syncthreads();                                                              \
    }

// Batched power: Ppow[dst+z] = Ppow[src+z] @ Ppow[pw]; also stores transpose.
__global__ __launch_bounds__(256) void k_pmul(int dst, int src, int pw) {
    const int z = blockIdx.z;
    const float* A = g_Ppow + (size_t)(src + z) * 65536;
    const float* B = g_Ppow + (size_t)pw * 65536;
    float* Cm = g_Ppow + (size_t)(dst + z) * 65536;
    float* Ct = g_Ppt + (size_t)(dst + z) * 65536;
    const int r0 = blockIdx.y * 64, c0 = blockIdx.x * 64;
    GEMM_BODY(A[(size_t)(r0 + row) * 256 + k0 + kq],
              B[(size_t)(k0 + row) * 256 + c0 + kq])
#pragma unroll
    for (int i = 0; i < 4; i++) {
        *(float4*)&Cm[(size_t)(r0 + ty * 4 + i) * 256 + c0 + tx * 4] =
            make_float4(acc[i][0], acc[i][1], acc[i][2], acc[i][3]);
#pragma unroll
        for (int j = 0; j < 4; j++)
            Ct[(size_t)(c0 + tx * 4 + j) * 256 + r0 + ty * 4 + i] = acc[i][j];
    }
}

__device__ __forceinline__ const float* Qptr(int k) {
    return (k == 1) ? (g_Ppow + (size_t)63 * 65536) : (g_Q + (size_t)k * 65536);
}

// Batched Q powers: Q^(dst0+z) = Q^(src0+z) @ Q^pw  (fp32)
__global__ __launch_bounds__(256) void k_qmul(int dst0, int src0, int pw) {
    const int z = blockIdx.z;
    const float* A = Qptr(src0 + z);
    const float* B = Qptr(pw);
    float* Cm = g_Q + (size_t)(dst0 + z) * 65536;
    const int r0 = blockIdx.y * 64, c0 = blockIdx.x * 64;
    GEMM_BODY(A[(size_t)(r0 + row) * 256 + k0 + kq],
              B[(size_t)(k0 + row) * 256 + c0 + kq])
#pragma unroll
    for (int i = 0; i < 4; i++)
        *(float4*)&Cm[(size_t)(r0 + ty * 4 + i) * 256 + c0 + tx * 4] =
            make_float4(acc[i][0], acc[i][1], acc[i][2], acc[i][3]);
}

// All backbones in one launch: p[64k] = p0 @ Q^k, k = blockIdx.y+1 (fp32)
__global__ __launch_bounds__(256) void k_bb_all() {
    const int k = blockIdx.y + 1;
    const float* A = g_p;
    const float* B = Qptr(k);
    float* Cm = g_p + (size_t)(64 * k) * 16384;
    const int c0 = blockIdx.x * 64;
    GEMM_BODY(A[(size_t)row * 256 + k0 + kq],
              B[(size_t)(k0 + row) * 256 + c0 + kq])
#pragma unroll
    for (int i = 0; i < 4; i++)
        *(float4*)&Cm[(size_t)(ty * 4 + i) * 256 + c0 + tx * 4] =
            make_float4(acc[i][0], acc[i][1], acc[i][2], acc[i][3]);
}

// ================= tf32 mma.sync =================
__device__ __forceinline__ void mma_tf32(float* c, const uint32_t* a, const uint32_t* b) {
    asm volatile(
        "mma.sync.aligned.m16n8k8.row.col.f32.tf32.tf32.f32 "
        "{%0,%1,%2,%3}, {%4,%5,%6,%7}, {%8,%9}, {%0,%1,%2,%3};"
        : "+f"(c[0]), "+f"(c[1]), "+f"(c[2]), "+f"(c[3])
        : "r"(a[0]), "r"(a[1]), "r"(a[2]), "r"(a[3]), "r"(b[0]), "r"(b[1]));
}

// Fill via MMA: p_t[64 x 128-tile] = p_base[64,256] @ P^i, hid = log(p_t)
// grid: (2 N-tiles, 499 t), 256 threads = 8 warps (2 M x 4 N)
__global__ __launch_bounds__(256) void k_fill_mma(float* __restrict__ hid) {
    __shared__ float sA[64][36];
    __shared__ float sB[128][36];
    const int u = threadIdx.x;
    const int lane = u & 31;
    const int w = u >> 5;
    const int wm = w & 1;
    const int wn = w >> 1;
    const int t = blockIdx.y + 1;
    const int base = ((t - 1) >> 6) << 6;
    const int i = t - base;
    const float* A = g_p + (size_t)base * 16384;
    const float* Bt = g_Ppt + (size_t)(i - 1) * 65536;
    const int c0 = blockIdx.x * 128;

    float acc[2][4][4];
#pragma unroll
    for (int mt = 0; mt < 2; mt++)
#pragma unroll
        for (int nt = 0; nt < 4; nt++)
#pragma unroll
            for (int r = 0; r < 4; r++) acc[mt][nt][r] = 0.f;

    const int lr = lane >> 2;
    const int lc = lane & 3;

    for (int ch = 0; ch < 8; ch++) {
        const int k0 = ch * 32;
#pragma unroll
        for (int q = 0; q < 2; q++) {
            int f = q * 256 + u;
            int row = f >> 3, c4 = (f & 7) << 2;
            *(float4*)&sA[row][c4] = *(const float4*)&A[(size_t)row * 256 + k0 + c4];
        }
#pragma unroll
        for (int q = 0; q < 4; q++) {
            int f = q * 256 + u;
            int row = f >> 3, c4 = (f & 7) << 2;
            *(float4*)&sB[row][c4] = *(const float4*)&Bt[(size_t)(c0 + row) * 256 + k0 + c4];
        }
        __syncthreads();
#pragma unroll
        for (int k8 = 0; k8 < 4; k8++) {
            const int kb = k8 * 8;
            uint32_t bfr[4][2];
#pragma unroll
            for (int nt = 0; nt < 4; nt++) {
                const int nrow = wn * 32 + nt * 8 + lr;
                bfr[nt][0] = __float_as_uint(sB[nrow][kb + lc]);
                bfr[nt][1] = __float_as_uint(sB[nrow][kb + lc + 4]);
            }
#pragma unroll
            for (int mt = 0; mt < 2; mt++) {
                const int arow = wm * 32 + mt * 16 + lr;
                uint32_t afr[4];
                afr[0] = __float_as_uint(sA[arow][kb + lc]);
                afr[1] = __float_as_uint(sA[arow + 8][kb + lc]);
                afr[2] = __float_as_uint(sA[arow][kb + lc + 4]);
                afr[3] = __float_as_uint(sA[arow + 8][kb + lc + 4]);
#pragma unroll
                for (int nt = 0; nt < 4; nt++) mma_tf32(acc[mt][nt], afr, bfr[nt]);
            }
        }
        __syncthreads();
    }

    float* pout = g_p + (size_t)t * 16384;
    float* hout = hid + (size_t)t * 16384;
#pragma unroll
    for (int mt = 0; mt < 2; mt++) {
        const int row = wm * 32 + mt * 16 + lr;
#pragma unroll
        for (int nt = 0; nt < 4; nt++) {
            const int col = c0 + wn * 32 + nt * 8 + 2 * lc;
            float2 v0 = make_float2(acc[mt][nt][0], acc[mt][nt][1]);
            float2 v1 = make_float2(acc[mt][nt][2], acc[mt][nt][3]);
            *(float2*)&pout[(size_t)row * 256 + col] = v0;
            *(float2*)&pout[(size_t)(row + 8) * 256 + col] = v1;
            *(float2*)&hout[(size_t)row * 256 + col] = make_float2(__logf(v0.x), __logf(v0.y));
            *(float2*)&hout[(size_t)(row + 8) * 256 + col] = make_float2(__logf(v1.x), __logf(v1.y));
        }
    }
}

// wp[t,s] = sum_c w[t,c] * p_t[c,s]
__global__ void k_wsum() {
    int t = blockIdx.x, s = threadIdx.x;
    const float* p = g_p + (size_t)t * 16384;
    float a = 0.f;
#pragma unroll 8
    for (int c = 0; c < 64; c++) a += g_w[t * 64 + c] * p[c * 256 + s];
    g_wp[(size_t)t * 256 + s] = a;
}

// ================= emission GEMM: 128x128 tile + cp.async double buffer =================
// 8 warps (4M x 2N), warp tile 32x64, acc[2][8][4] = 64 regs.
// Dynamic SMEM: A[2][128][36], B[2][128][36], BM[128] = 74240 bytes
#define EMIS_SMEM_FLOATS (4 * 128 * 36 + 128)

__global__ __launch_bounds__(256) void k_emis_mma(float* __restrict__ out) {
    extern __shared__ float smdy[];
    float* sAb[2] = {smdy, smdy + 128 * 36};
    float* sBb[2] = {smdy + 2 * 128 * 36, smdy + 3 * 128 * 36};
    float* sBM = smdy + 4 * 128 * 36;

    const int u = threadIdx.x;
    const int lane = u & 31;
    const int w = u >> 5;
    const int wm = w & 3;     // 4 M-groups of 32 rows
    const int wn = w >> 2;    // 2 N-groups of 64 cols
    const int n0 = blockIdx.x * 128;
    const int r0 = blockIdx.y * 128;

    if (u < 128) sBM[u] = g_bmaxE[n0 + u];

#define EMIS_PREFETCH(ch, st)                                                          \
    {                                                                                  \
        const int k0_ = (ch) * 32;                                                     \
        _Pragma("unroll") for (int q = 0; q < 4; q++) {                                \
            int f = q * 256 + u;                                                       \
            int row = f >> 3, c4 = (f & 7) << 2;                                       \
            uint32_t da = (uint32_t)__cvta_generic_to_shared(&sAb[st][row * 36 + c4]); \
            asm volatile("cp.async.cg.shared.global [%0], [%1], 16;" ::                \
                         "r"(da), "l"(&g_p[(size_t)(r0 + row) * 256 + k0_ + c4]));     \
            uint32_t db = (uint32_t)__cvta_generic_to_shared(&sBb[st][row * 36 + c4]); \
            asm volatile("cp.async.cg.shared.global [%0], [%1], 16;" ::                \
                         "r"(db), "l"(&g_Et[(size_t)(n0 + row) * 256 + k0_ + c4]));    \
        }                                                                              \
        asm volatile("cp.async.commit_group;");                                        \
    }

    float acc[2][8][4];
#pragma unroll
    for (int mt = 0; mt < 2; mt++)
#pragma unroll
        for (int nt = 0; nt < 8; nt++)
#pragma unroll
            for (int r = 0; r < 4; r++) acc[mt][nt][r] = 0.f;

    const int lr = lane >> 2;
    const int lc = lane & 3;

    EMIS_PREFETCH(0, 0)

    for (int ch = 0; ch < 8; ch++) {
        if (ch < 7) {
            EMIS_PREFETCH(ch + 1, (ch + 1) & 1)
            asm volatile("cp.async.wait_group 1;");
        } else {
            asm volatile("cp.async.wait_group 0;");
        }
        __syncthreads();
        const float* A = sAb[ch & 1];
        const float* B = sBb[ch & 1];
#pragma unroll
        for (int k8 = 0; k8 < 4; k8++) {
            const int kb = k8 * 8;
            uint32_t bfr[8][2];
#pragma unroll
            for (int nt = 0; nt < 8; nt++) {
                const int nrow = wn * 64 + nt * 8 + lr;
                bfr[nt][0] = __float_as_uint(B[nrow * 36 + kb + lc]);
                bfr[nt][1] = __float_as_uint(B[nrow * 36 + kb + lc + 4]);
            }
#pragma unroll
            for (int mt = 0; mt < 2; mt++) {
                const int arow = wm * 32 + mt * 16 + lr;
                uint32_t afr[4];
                afr[0] = __float_as_uint(A[arow * 36 + kb + lc]);
                afr[1] = __float_as_uint(A[(arow + 8) * 36 + kb + lc]);
                afr[2] = __float_as_uint(A[arow * 36 + kb + lc + 4]);
                afr[3] = __float_as_uint(A[(arow + 8) * 36 + kb + lc + 4]);
#pragma unroll
                for (int nt = 0; nt < 8; nt++) mma_tf32(acc[mt][nt], afr, bfr[nt]);
            }
        }
        __syncthreads();
    }
#undef EMIS_PREFETCH

    float* obsp = out + 1000000u;
#pragma unroll
    for (int mt = 0; mt < 2; mt++) {
        const int row = r0 + wm * 32 + mt * 16 + lr;
#pragma unroll
        for (int nt = 0; nt < 8; nt++) {
            const int col = wn * 64 + nt * 8 + 2 * lc;
            const int n = n0 + col;
            if (n < 2000) {
                float2 v0, v1;
                v0.x = __logf(acc[mt][nt][0]) + sBM[col];
                v0.y = __logf(acc[mt][nt][1]) + sBM[col + 1];
                v1.x = __logf(acc[mt][nt][2]) + sBM[col];
                v1.y = __logf(acc[mt][nt][3]) + sBM[col + 1];
                *(float2*)&obsp[(size_t)row * 2000 + n] = v0;
                *(float2*)&obsp[(size_t)(row + 8) * 2000 + n] = v1;
            }
        }
    }
}

// log_obs[t,n] = log( sum_s wp[t,s]*Ee[s,n] ) + bm[n]
__global__ __launch_bounds__(256) void k_obs(float* __restrict__ out) {
    __shared__ float wsm[8 * 256];
    const int t0 = blockIdx.y * 8;
    const int n = blockIdx.x * 256 + threadIdx.x;
#pragma unroll
    for (int j = 0; j < 8; j++)
        wsm[j * 256 + threadIdx.x] =
            (t0 + j < 500) ? g_wp[(size_t)(t0 + j) * 256 + threadIdx.x] : 0.f;
    __syncthreads();
    float acc[8];
#pragma unroll
    for (int j = 0; j < 8; j++) acc[j] = 0.f;
    for (int s = 0; s < 256; s++) {
        float e = (n < 2000) ? g_E[(size_t)s * 2000 + n] : 0.f;
#pragma unroll
        for (int j = 0; j < 8; j++) acc[j] += wsm[j * 256 + s] * e;
    }
    if (n < 2000) {
        float bm = g_bmaxE[n];
#pragma unroll
        for (int j = 0; j < 8; j++)
            if (t0 + j < 500) out[(size_t)(t0 + j) * 2000 + n] = __logf(acc[j]) + bm;
    }
}

// ================= launch =================
extern "C" void kernel_launch(void* const* d_in, const int* in_sizes, int n_in,
                              void* d_out, int out_size) {
    const float* usi = (const float*)d_in[0];  // [64,256]
    const float* ucw = (const float*)d_in[1];  // [500,64]
    const float* uem = (const float*)d_in[2];  // [256,2000]
    const float* utm = (const float*)d_in[3];  // [256,256]
    const float* msk = (const float*)d_in[4];  // [256,2000]
    float* out = (float*)d_out;
    float* hid = out + 65000000u;

    const int emis_smem = EMIS_SMEM_FLOATS * 4;
    cudaFuncSetAttribute(k_emis_mma, cudaFuncAttributeMaxDynamicSharedMemorySize, emis_smem);

    k_softmax_P<<<256, 256>>>(utm);
    k_softmax_p0<<<64, 256>>>(usi, hid);
    k_softmax_w<<<500, 64>>>(ucw);
    k_Erow<<<256, 256>>>(uem, msk);
    k_Ecol<<<8, 256>>>();

    // P^1..P^64 by batched doubling (fp32, also stores transposes)
    k_pmul<<<dim3(4, 4, 1), 256>>>(1, 0, 0);
    k_pmul<<<dim3(4, 4, 2), 256>>>(2, 0, 1);
    k_pmul<<<dim3(4, 4, 4), 256>>>(4, 0, 3);
    k_pmul<<<dim3(4, 4, 8), 256>>>(8, 0, 7);
    k_pmul<<<dim3(4, 4, 16), 256>>>(16, 0, 15);
    k_pmul<<<dim3(4, 4, 32), 256>>>(32, 0, 31);

    // Q = P^64; Q^2..Q^7 via batched doubling (fp32)
    k_qmul<<<dim3(4, 4, 1), 256>>>(2, 1, 1);  // Q^2
    k_qmul<<<dim3(4, 4, 2), 256>>>(3, 1, 2);  // Q^3, Q^4
    k_qmul<<<dim3(4, 4, 3), 256>>>(5, 1, 4);  // Q^5, Q^6, Q^7

    // all backbones p[64k] = p0 @ Q^k in one launch
    k_bb_all<<<dim3(4, 7), 256>>>();

    // all t = 1..499 via tf32 MMA (writes p and log_hidden)
    k_fill_mma<<<dim3(2, 499), 256>>>(hid);

    k_wsum<<<500, 256>>>();
    k_emis_mma<<<dim3(16, 250), 256, emis_smem>>>(out);
    k_obs<<<dim3(8, 63), 256>>>(out);
}

// round 7
// speedup vs baseline: 1.0886x; 1.0295x over previous
#include <cuda_runtime.h>
#include <cstdint>

// Problem dims: C=64, S=256, T=500, N=2000
// Output layout (concatenated, float32):
//   log_obs    [T,N]      at offset 0            (1,000,000)
//   log_obs_   [T,C,N]    at offset 1,000,000    (64,000,000)
//   log_hidden [T,C,S]    at offset 65,000,000   (8,192,000)

static __device__ float g_Ppow[64 * 256 * 256];   // g_Ppow[i] = P^(i+1), i=0..63
static __device__ float g_Ppt[64 * 256 * 256];    // transposed powers
static __device__ float g_Q[8 * 256 * 256];       // Q^k = P^(64k), slots 2..7
static __device__ float g_p[500 * 64 * 256];      // probabilities p_t  [T][C][S]
static __device__ float g_E[256 * 2000];          // E, then Ee = E/colmax in place
static __device__ float g_Et[2048 * 256];         // Ee transposed [N_pad][S], zero padded
static __device__ float g_bmaxE[2048];            // log(colmax of E)
static __device__ float g_w[500 * 64];            // softmax chain weights
static __device__ float g_wp[500 * 256];          // wp[t,s] = sum_c w[t,c] p_t[c,s]

// ================= block reductions =================
__device__ __forceinline__ float bredMax(float v) {
    __shared__ float sm[8];
    unsigned nw = blockDim.x >> 5;
#pragma unroll
    for (int o = 16; o; o >>= 1) v = fmaxf(v, __shfl_xor_sync(0xffffffffu, v, o));
    if ((threadIdx.x & 31) == 0) sm[threadIdx.x >> 5] = v;
    __syncthreads();
    if (threadIdx.x < 32) {
        v = (threadIdx.x < nw) ? sm[threadIdx.x] : -3.402823e38f;
#pragma unroll
        for (int o = 4; o; o >>= 1) v = fmaxf(v, __shfl_xor_sync(0xffffffffu, v, o));
        if (threadIdx.x == 0) sm[0] = v;
    }
    __syncthreads();
    v = sm[0];
    __syncthreads();
    return v;
}
__device__ __forceinline__ float bredSum(float v) {
    __shared__ float sm[8];
    unsigned nw = blockDim.x >> 5;
#pragma unroll
    for (int o = 16; o; o >>= 1) v += __shfl_xor_sync(0xffffffffu, v, o);
    if ((threadIdx.x & 31) == 0) sm[threadIdx.x >> 5] = v;
    __syncthreads();
    if (threadIdx.x < 32) {
        v = (threadIdx.x < nw) ? sm[threadIdx.x] : 0.f;
#pragma unroll
        for (int o = 4; o; o >>= 1) v += __shfl_xor_sync(0xffffffffu, v, o);
        if (threadIdx.x == 0) sm[0] = v;
    }
    __syncthreads();
    v = sm[0];
    __syncthreads();
    return v;
}

// ================= preprocessing =================
__global__ void k_softmax_P(const float* __restrict__ x) {
    int r = blockIdx.x;
    float v = x[r * 256 + threadIdx.x];
    float m = bredMax(v);
    float e = __expf(v - m);
    float Z = bredSum(e);
    float p = e / Z;
    g_Ppow[r * 256 + threadIdx.x] = p;
    g_Ppt[threadIdx.x * 256 + r] = p;
}
__global__ void k_softmax_p0(const float* __restrict__ x, float* __restrict__ hid) {
    int r = blockIdx.x;
    float v = x[r * 256 + threadIdx.x];
    float m = bredMax(v);
    float e = __expf(v - m);
    float Z = bredSum(e);
    g_p[r * 256 + threadIdx.x] = e / Z;
    hid[r * 256 + threadIdx.x] = (v - m) - __logf(Z);
}
__global__ void k_softmax_w(const float* __restrict__ x) {
    int r = blockIdx.x;
    float v = x[r * 64 + threadIdx.x];
    float m = bredMax(v);
    float e = __expf(v - m);
    float Z = bredSum(e);
    g_w[r * 64 + threadIdx.x] = e / Z;
}
__global__ void k_Erow(const float* __restrict__ x, const float* __restrict__ mask) {
    int s = blockIdx.x;
    const float* xr = x + (size_t)s * 2000;
    const float* mr = mask + (size_t)s * 2000;
    float* Er = g_E + (size_t)s * 2000;
    float m = -3.402823e38f;
    for (int n = threadIdx.x; n < 2000; n += 256)
        if (mr[n] > 0.f) m = fmaxf(m, xr[n]);
    m = bredMax(m);
    float sloc = 0.f;
    for (int n = threadIdx.x; n < 2000; n += 256) {
        float e = (mr[n] > 0.f) ? __expf(xr[n] - m) * mr[n] : 0.f;
        Er[n] = e;
        sloc += e;
    }
    float Z = bredSum(sloc);
    float inv = 1.f / Z;
    for (int n = threadIdx.x; n < 2000; n += 256) Er[n] *= inv;
}
// colmax + rescale + transpose fused
__global__ void k_Ecol() {
    int n = blockIdx.x * 256 + threadIdx.x;
    if (n >= 2000) return;
    float m = 0.f;
    for (int s = 0; s < 256; s++) m = fmaxf(m, g_E[(size_t)s * 2000 + n]);
    g_bmaxE[n] = __logf(m);
    float inv = 1.f / m;
    for (int s = 0; s < 256; s++) {
        float v = g_E[(size_t)s * 2000 + n] * inv;
        g_E[(size_t)s * 2000 + n] = v;
        g_Et[(size_t)n * 256 + s] = v;
    }
}

// ================= SIMT 64x64xK=256 GEMM core (macro body) =================
#define GEMM_BODY(Aexpr, Bexpr)                                                       \
    __shared__ float As[64][68];                                                      \
    __shared__ float Bs[64][68];                                                      \
    const int u = threadIdx.x;                                                        \
    const int tx = u & 15, ty = u >> 4;                                               \
    float acc[4][4];                                                                  \
    _Pragma("unroll") for (int i = 0; i < 4; i++)                                     \
        _Pragma("unroll") for (int j = 0; j < 4; j++) acc[i][j] = 0.f;                \
    for (int k0 = 0; k0 < 256; k0 += 64) {                                            \
        _Pragma("unroll") for (int q = 0; q < 4; q++) {                               \
            int f = q * 256 + u;                                                      \
            int row = f >> 4, kq = (f & 15) << 2;                                     \
            *(float4*)&As[row][kq] = *(const float4*)&(Aexpr);                        \
            *(float4*)&Bs[row][kq] = *(const float4*)&(Bexpr);                        \
        }                                                                             \
        __syncthreads();                                                              \
        _Pragma("unroll") for (int k2 = 0; k2 < 64; k2++) {                           \
            float a0 = As[ty * 4 + 0][k2], a1 = As[ty * 4 + 1][k2];                   \
            float a2 = As[ty * 4 + 2][k2], a3 = As[ty * 4 + 3][k2];                   \
            float4 b = *(const float4*)&Bs[k2][tx * 4];                               \
            acc[0][0] += a0 * b.x; acc[0][1] += a0 * b.y; acc[0][2] += a0 * b.z; acc[0][3] += a0 * b.w; \
            acc[1][0] += a1 * b.x; acc[1][1] += a1 * b.y; acc[1][2] += a1 * b.z; acc[1][3] += a1 * b.w; \
            acc[2][0] += a2 * b.x; acc[2][1] += a2 * b.y; acc[2][2] += a2 * b.z; acc[2][3] += a2 * b.w; \
            acc[3][0] += a3 * b.x; acc[3][1] += a3 * b.y; acc[3][2] += a3 * b.z; acc[3][3] += a3 * b.w; \
        }                                                                             \
        __syncthreads();                                                              \
    }

// Batched power: Ppow[dst+z] = Ppow[src+z] @ Ppow[pw]; also stores transpose.
__global__ __launch_bounds__(256) void k_pmul(int dst, int src, int pw) {
    const int z = blockIdx.z;
    const float* A = g_Ppow + (size_t)(src + z) * 65536;
    const float* B = g_Ppow + (size_t)pw * 65536;
    float* Cm = g_Ppow + (size_t)(dst + z) * 65536;
    float* Ct = g_Ppt + (size_t)(dst + z) * 65536;
    const int r0 = blockIdx.y * 64, c0 = blockIdx.x * 64;
    GEMM_BODY(A[(size_t)(r0 + row) * 256 + k0 + kq],
              B[(size_t)(k0 + row) * 256 + c0 + kq])
#pragma unroll
    for (int i = 0; i < 4; i++) {
        *(float4*)&Cm[(size_t)(r0 + ty * 4 + i) * 256 + c0 + tx * 4] =
            make_float4(acc[i][0], acc[i][1], acc[i][2], acc[i][3]);
#pragma unroll
        for (int j = 0; j < 4; j++)
            Ct[(size_t)(c0 + tx * 4 + j) * 256 + r0 + ty * 4 + i] = acc[i][j];
    }
}

__device__ __forceinline__ const float* Qptr(int k) {
    return (k == 1) ? (g_Ppow + (size_t)63 * 65536) : (g_Q + (size_t)k * 65536);
}

// Batched Q powers: Q^(dst0+z) = Q^(src0+z) @ Q^pw  (fp32)
__global__ __launch_bounds__(256) void k_qmul(int dst0, int src0, int pw) {
    const int z = blockIdx.z;
    const float* A = Qptr(src0 + z);
    const float* B = Qptr(pw);
    float* Cm = g_Q + (size_t)(dst0 + z) * 65536;
    const int r0 = blockIdx.y * 64, c0 = blockIdx.x * 64;
    GEMM_BODY(A[(size_t)(r0 + row) * 256 + k0 + kq],
              B[(size_t)(k0 + row) * 256 + c0 + kq])
#pragma unroll
    for (int i = 0; i < 4; i++)
        *(float4*)&Cm[(size_t)(r0 + ty * 4 + i) * 256 + c0 + tx * 4] =
            make_float4(acc[i][0], acc[i][1], acc[i][2], acc[i][3]);
}

// All backbones in one launch: p[64k] = p0 @ Q^k, k = blockIdx.y+1 (fp32)
__global__ __launch_bounds__(256) void k_bb_all() {
    const int k = blockIdx.y + 1;
    const float* A = g_p;
    const float* B = Qptr(k);
    float* Cm = g_p + (size_t)(64 * k) * 16384;
    const int c0 = blockIdx.x * 64;
    GEMM_BODY(A[(size_t)row * 256 + k0 + kq],
              B[(size_t)(k0 + row) * 256 + c0 + kq])
#pragma unroll
    for (int i = 0; i < 4; i++)
        *(float4*)&Cm[(size_t)(ty * 4 + i) * 256 + c0 + tx * 4] =
            make_float4(acc[i][0], acc[i][1], acc[i][2], acc[i][3]);
}

// ================= tf32 mma.sync =================
__device__ __forceinline__ void mma_tf32(float* c, const uint32_t* a, const uint32_t* b) {
    asm volatile(
        "mma.sync.aligned.m16n8k8.row.col.f32.tf32.tf32.f32 "
        "{%0,%1,%2,%3}, {%4,%5,%6,%7}, {%8,%9}, {%0,%1,%2,%3};"
        : "+f"(c[0]), "+f"(c[1]), "+f"(c[2]), "+f"(c[3])
        : "r"(a[0]), "r"(a[1]), "r"(a[2]), "r"(a[3]), "r"(b[0]), "r"(b[1]));
}

// Fill via MMA: p_t[64 x 128-tile] = p_base[64,256] @ P^i, hid = log(p_t)
// grid: (2 N-tiles, 499 t), 256 threads = 8 warps (2 M x 4 N)
__global__ __launch_bounds__(256) void k_fill_mma(float* __restrict__ hid) {
    __shared__ float sA[64][36];
    __shared__ float sB[128][36];
    const int u = threadIdx.x;
    const int lane = u & 31;
    const int w = u >> 5;
    const int wm = w & 1;
    const int wn = w >> 1;
    const int t = blockIdx.y + 1;
    const int base = ((t - 1) >> 6) << 6;
    const int i = t - base;
    const float* A = g_p + (size_t)base * 16384;
    const float* Bt = g_Ppt + (size_t)(i - 1) * 65536;
    const int c0 = blockIdx.x * 128;

    float acc[2][4][4];
#pragma unroll
    for (int mt = 0; mt < 2; mt++)
#pragma unroll
        for (int nt = 0; nt < 4; nt++)
#pragma unroll
            for (int r = 0; r < 4; r++) acc[mt][nt][r] = 0.f;

    const int lr = lane >> 2;
    const int lc = lane & 3;

    for (int ch = 0; ch < 8; ch++) {
        const int k0 = ch * 32;
#pragma unroll
        for (int q = 0; q < 2; q++) {
            int f = q * 256 + u;
            int row = f >> 3, c4 = (f & 7) << 2;
            *(float4*)&sA[row][c4] = *(const float4*)&A[(size_t)row * 256 + k0 + c4];
        }
#pragma unroll
        for (int q = 0; q < 4; q++) {
            int f = q * 256 + u;
            int row = f >> 3, c4 = (f & 7) << 2;
            *(float4*)&sB[row][c4] = *(const float4*)&Bt[(size_t)(c0 + row) * 256 + k0 + c4];
        }
        __syncthreads();
#pragma unroll
        for (int k8 = 0; k8 < 4; k8++) {
            const int kb = k8 * 8;
            uint32_t bfr[4][2];
#pragma unroll
            for (int nt = 0; nt < 4; nt++) {
                const int nrow = wn * 32 + nt * 8 + lr;
                bfr[nt][0] = __float_as_uint(sB[nrow][kb + lc]);
                bfr[nt][1] = __float_as_uint(sB[nrow][kb + lc + 4]);
            }
#pragma unroll
            for (int mt = 0; mt < 2; mt++) {
                const int arow = wm * 32 + mt * 16 + lr;
                uint32_t afr[4];
                afr[0] = __float_as_uint(sA[arow][kb + lc]);
                afr[1] = __float_as_uint(sA[arow + 8][kb + lc]);
                afr[2] = __float_as_uint(sA[arow][kb + lc + 4]);
                afr[3] = __float_as_uint(sA[arow + 8][kb + lc + 4]);
#pragma unroll
                for (int nt = 0; nt < 4; nt++) mma_tf32(acc[mt][nt], afr, bfr[nt]);
            }
        }
        __syncthreads();
    }

    float* pout = g_p + (size_t)t * 16384;
    float* hout = hid + (size_t)t * 16384;
#pragma unroll
    for (int mt = 0; mt < 2; mt++) {
        const int row = wm * 32 + mt * 16 + lr;
#pragma unroll
        for (int nt = 0; nt < 4; nt++) {
            const int col = c0 + wn * 32 + nt * 8 + 2 * lc;
            float2 v0 = make_float2(acc[mt][nt][0], acc[mt][nt][1]);
            float2 v1 = make_float2(acc[mt][nt][2], acc[mt][nt][3]);
            *(float2*)&pout[(size_t)row * 256 + col] = v0;
            *(float2*)&pout[(size_t)(row + 8) * 256 + col] = v1;
            *(float2*)&hout[(size_t)row * 256 + col] = make_float2(__logf(v0.x), __logf(v0.y));
            *(float2*)&hout[(size_t)(row + 8) * 256 + col] = make_float2(__logf(v1.x), __logf(v1.y));
        }
    }
}

// wp[t,s] = sum_c w[t,c] * p_t[c,s]
__global__ void k_wsum() {
    int t = blockIdx.x, s = threadIdx.x;
    const float* p = g_p + (size_t)t * 16384;
    float a = 0.f;
#pragma unroll 8
    for (int c = 0; c < 64; c++) a += g_w[t * 64 + c] * p[c * 256 + s];
    g_wp[(size_t)t * 256 + s] = a;
}

// ================= emission GEMM via mma.sync tf32 (R4 proven version) =================
// D[128,128] = p_rows[128,256] @ Et_rows[128,256]^T
// grid: (16 N-tiles, 250 M-tiles), 256 threads = 8 warps (4 M x 2 N)
__global__ __launch_bounds__(256) void k_emis_mma(float* __restrict__ out) {
    __shared__ float sA[128][36];
    __shared__ float sB[128][36];
    __shared__ float sBM[128];

    const int u = threadIdx.x;
    const int lane = u & 31;
    const int w = u >> 5;
    const int wm = w & 3;
    const int wn = w >> 2;
    const int n0 = blockIdx.x * 128;
    const int r0 = blockIdx.y * 128;

    if (u < 128) sBM[u] = g_bmaxE[n0 + u];

    float acc[2][8][4];
#pragma unroll
    for (int mt = 0; mt < 2; mt++)
#pragma unroll
        for (int nt = 0; nt < 8; nt++)
#pragma unroll
            for (int r = 0; r < 4; r++) acc[mt][nt][r] = 0.f;

    const int lr = lane >> 2;
    const int lc = lane & 3;

    for (int ch = 0; ch < 8; ch++) {
        const int k0 = ch * 32;
#pragma unroll
        for (int q = 0; q < 4; q++) {
            int f = q * 256 + u;
            int row = f >> 3, c4 = (f & 7) << 2;
            *(float4*)&sA[row][c4] = *(const float4*)&g_p[(size_t)(r0 + row) * 256 + k0 + c4];
            *(float4*)&sB[row][c4] = *(const float4*)&g_Et[(size_t)(n0 + row) * 256 + k0 + c4];
        }
        __syncthreads();
#pragma unroll
        for (int k8 = 0; k8 < 4; k8++) {
            const int kb = k8 * 8;
            uint32_t bfr[8][2];
#pragma unroll
            for (int nt = 0; nt < 8; nt++) {
                const int nrow = wn * 64 + nt * 8 + lr;
                bfr[nt][0] = __float_as_uint(sB[nrow][kb + lc]);
                bfr[nt][1] = __float_as_uint(sB[nrow][kb + lc + 4]);
            }
#pragma unroll
            for (int mt = 0; mt < 2; mt++) {
                const int arow = wm * 32 + mt * 16 + lr;
                uint32_t afr[4];
                afr[0] = __float_as_uint(sA[arow][kb + lc]);
                afr[1] = __float_as_uint(sA[arow + 8][kb + lc]);
                afr[2] = __float_as_uint(sA[arow][kb + lc + 4]);
                afr[3] = __float_as_uint(sA[arow + 8][kb + lc + 4]);
#pragma unroll
                for (int nt = 0; nt < 8; nt++) mma_tf32(acc[mt][nt], afr, bfr[nt]);
            }
        }
        __syncthreads();
    }

    float* obsp = out + 1000000u;
#pragma unroll
    for (int mt = 0; mt < 2; mt++) {
        const int row = r0 + wm * 32 + mt * 16 + lr;
#pragma unroll
        for (int nt = 0; nt < 8; nt++) {
            const int col = wn * 64 + nt * 8 + 2 * lc;
            const int n = n0 + col;
            if (n < 2000) {
                float2 v0, v1;
                v0.x = __logf(acc[mt][nt][0]) + sBM[col];
                v0.y = __logf(acc[mt][nt][1]) + sBM[col + 1];
                v1.x = __logf(acc[mt][nt][2]) + sBM[col];
                v1.y = __logf(acc[mt][nt][3]) + sBM[col + 1];
                *(float2*)&obsp[(size_t)row * 2000 + n] = v0;
                *(float2*)&obsp[(size_t)(row + 8) * 2000 + n] = v1;
            }
        }
    }
}

// log_obs[t,n] = log( sum_s wp[t,s]*Ee[s,n] ) + bm[n]
__global__ __launch_bounds__(256) void k_obs(float* __restrict__ out) {
    __shared__ float wsm[8 * 256];
    const int t0 = blockIdx.y * 8;
    const int n = blockIdx.x * 256 + threadIdx.x;
#pragma unroll
    for (int j = 0; j < 8; j++)
        wsm[j * 256 + threadIdx.x] =
            (t0 + j < 500) ? g_wp[(size_t)(t0 + j) * 256 + threadIdx.x] : 0.f;
    __syncthreads();
    float acc[8];
#pragma unroll
    for (int j = 0; j < 8; j++) acc[j] = 0.f;
    for (int s = 0; s < 256; s++) {
        float e = (n < 2000) ? g_E[(size_t)s * 2000 + n] : 0.f;
#pragma unroll
        for (int j = 0; j < 8; j++) acc[j] += wsm[j * 256 + s] * e;
    }
    if (n < 2000) {
        float bm = g_bmaxE[n];
#pragma unroll
        for (int j = 0; j < 8; j++)
            if (t0 + j < 500) out[(size_t)(t0 + j) * 2000 + n] = __logf(acc[j]) + bm;
    }
}

// ================= launch =================
extern "C" void kernel_launch(void* const* d_in, const int* in_sizes, int n_in,
                              void* d_out, int out_size) {
    const float* usi = (const float*)d_in[0];  // [64,256]
    const float* ucw = (const float*)d_in[1];  // [500,64]
    const float* uem = (const float*)d_in[2];  // [256,2000]
    const float* utm = (const float*)d_in[3];  // [256,256]
    const float* msk = (const float*)d_in[4];  // [256,2000]
    float* out = (float*)d_out;
    float* hid = out + 65000000u;

    k_softmax_P<<<256, 256>>>(utm);
    k_softmax_p0<<<64, 256>>>(usi, hid);
    k_softmax_w<<<500, 64>>>(ucw);
    k_Erow<<<256, 256>>>(uem, msk);
    k_Ecol<<<8, 256>>>();

    // P^1..P^64 by batched doubling (fp32, also stores transposes)
    k_pmul<<<dim3(4, 4, 1), 256>>>(1, 0, 0);
    k_pmul<<<dim3(4, 4, 2), 256>>>(2, 0, 1);
    k_pmul<<<dim3(4, 4, 4), 256>>>(4, 0, 3);
    k_pmul<<<dim3(4, 4, 8), 256>>>(8, 0, 7);
    k_pmul<<<dim3(4, 4, 16), 256>>>(16, 0, 15);
    k_pmul<<<dim3(4, 4, 32), 256>>>(32, 0, 31);

    // Q = P^64; Q^2..Q^7 via batched doubling (fp32)
    k_qmul<<<dim3(4, 4, 1), 256>>>(2, 1, 1);  // Q^2
    k_qmul<<<dim3(4, 4, 2), 256>>>(3, 1, 2);  // Q^3, Q^4
    k_qmul<<<dim3(4, 4, 3), 256>>>(5, 1, 4);  // Q^5, Q^6, Q^7

    // all backbones p[64k] = p0 @ Q^k in one launch
    k_bb_all<<<dim3(4, 7), 256>>>();

    // all t = 1..499 via tf32 MMA (writes p and log_hidden)
    k_fill_mma<<<dim3(2, 499), 256>>>(hid);

    k_wsum<<<500, 256>>>();
    k_emis_mma<<<dim3(16, 250), 256>>>(out);
    k_obs<<<dim3(8, 63), 256>>>(out);
}

// round 8
// speedup vs baseline: 1.1957x; 1.0984x over previous
#include <cuda_runtime.h>
#include <cstdint>

// Problem dims: C=64, S=256, T=500, N=2000
// Output layout (concatenated, float32):
//   log_obs    [T,N]      at offset 0            (1,000,000)
//   log_obs_   [T,C,N]    at offset 1,000,000    (64,000,000)
//   log_hidden [T,C,S]    at offset 65,000,000   (8,192,000)

static __device__ float g_Ppow[64 * 256 * 256];   // g_Ppow[i] = P^(i+1), i=0..63
static __device__ float g_Ppt[64 * 256 * 256];    // transposed powers
static __device__ float g_Q[8 * 256 * 256];       // Q^k = P^(64k), slots 2..7
static __device__ float g_p[500 * 64 * 256];      // probabilities p_t  [T][C][S]
static __device__ float g_E[256 * 2000];          // E, then Ee = E/colmax in place
static __device__ float g_Et[2048 * 256];         // Ee transposed [N_pad][S], zero padded
static __device__ float g_bmaxE[2048];            // log(colmax of E)
static __device__ float g_w[500 * 64];            // softmax chain weights
static __device__ float g_wp[500 * 256];          // wp[t,s] = sum_c w[t,c] p_t[c,s]

// ================= block reductions =================
__device__ __forceinline__ float bredMax(float v) {
    __shared__ float sm[8];
    unsigned nw = blockDim.x >> 5;
#pragma unroll
    for (int o = 16; o; o >>= 1) v = fmaxf(v, __shfl_xor_sync(0xffffffffu, v, o));
    if ((threadIdx.x & 31) == 0) sm[threadIdx.x >> 5] = v;
    __syncthreads();
    if (threadIdx.x < 32) {
        v = (threadIdx.x < nw) ? sm[threadIdx.x] : -3.402823e38f;
#pragma unroll
        for (int o = 4; o; o >>= 1) v = fmaxf(v, __shfl_xor_sync(0xffffffffu, v, o));
        if (threadIdx.x == 0) sm[0] = v;
    }
    __syncthreads();
    v = sm[0];
    __syncthreads();
    return v;
}
__device__ __forceinline__ float bredSum(float v) {
    __shared__ float sm[8];
    unsigned nw = blockDim.x >> 5;
#pragma unroll
    for (int o = 16; o; o >>= 1) v += __shfl_xor_sync(0xffffffffu, v, o);
    if ((threadIdx.x & 31) == 0) sm[threadIdx.x >> 5] = v;
    __syncthreads();
    if (threadIdx.x < 32) {
        v = (threadIdx.x < nw) ? sm[threadIdx.x] : 0.f;
#pragma unroll
        for (int o = 4; o; o >>= 1) v += __shfl_xor_sync(0xffffffffu, v, o);
        if (threadIdx.x == 0) sm[0] = v;
    }
    __syncthreads();
    v = sm[0];
    __syncthreads();
    return v;
}

// ================= fused preprocessing =================
// blocks [0,256): P rows; [256,320): p0 rows; [320,383): chain weights (8 rows/block)
__global__ void k_pre(const float* __restrict__ usi, const float* __restrict__ ucw,
                      const float* __restrict__ utm, float* __restrict__ hid) {
    const int b = blockIdx.x;
    const int u = threadIdx.x;
    if (b < 256) {
        float v = utm[b * 256 + u];
        float m = bredMax(v);
        float e = __expf(v - m);
        float Z = bredSum(e);
        float p = e / Z;
        g_Ppow[b * 256 + u] = p;
        g_Ppt[u * 256 + b] = p;
    } else if (b < 320) {
        int r = b - 256;
        float v = usi[r * 256 + u];
        float m = bredMax(v);
        float e = __expf(v - m);
        float Z = bredSum(e);
        g_p[r * 256 + u] = e / Z;
        hid[r * 256 + u] = (v - m) - __logf(Z);
    } else {
        int wid = u >> 5, lane = u & 31;
        int r = (b - 320) * 8 + wid;
        if (r < 500) {
            float v0 = ucw[r * 64 + lane], v1 = ucw[r * 64 + lane + 32];
            float m = fmaxf(v0, v1);
#pragma unroll
            for (int o = 16; o; o >>= 1) m = fmaxf(m, __shfl_xor_sync(0xffffffffu, m, o));
            float e0 = __expf(v0 - m), e1 = __expf(v1 - m);
            float s = e0 + e1;
#pragma unroll
            for (int o = 16; o; o >>= 1) s += __shfl_xor_sync(0xffffffffu, s, o);
            g_w[r * 64 + lane] = e0 / s;
            g_w[r * 64 + lane + 32] = e1 / s;
        }
    }
}

__global__ void k_Erow(const float* __restrict__ x, const float* __restrict__ mask) {
    int s = blockIdx.x;
    const float* xr = x + (size_t)s * 2000;
    const float* mr = mask + (size_t)s * 2000;
    float* Er = g_E + (size_t)s * 2000;
    float m = -3.402823e38f;
    for (int n = threadIdx.x; n < 2000; n += 256)
        if (mr[n] > 0.f) m = fmaxf(m, xr[n]);
    m = bredMax(m);
    float sloc = 0.f;
    for (int n = threadIdx.x; n < 2000; n += 256) {
        float e = (mr[n] > 0.f) ? __expf(xr[n] - m) * mr[n] : 0.f;
        Er[n] = e;
        sloc += e;
    }
    float Z = bredSum(sloc);
    float inv = 1.f / Z;
    for (int n = threadIdx.x; n < 2000; n += 256) Er[n] *= inv;
}
__global__ void k_Ecol() {
    int n = blockIdx.x * 256 + threadIdx.x;
    if (n >= 2000) return;
    float m = 0.f;
    for (int s = 0; s < 256; s++) m = fmaxf(m, g_E[(size_t)s * 2000 + n]);
    g_bmaxE[n] = __logf(m);
    float inv = 1.f / m;
    for (int s = 0; s < 256; s++) g_E[(size_t)s * 2000 + n] *= inv;
}
// Tiled transpose: g_Et[n][s] = g_E[s][n]. grid (63, 8), 256 threads.
// Rows n in [2016,2048) remain zero from static initialization.
__global__ void k_transposeE() {
    __shared__ float tile[32][33];
    const int nb = blockIdx.x * 32, sb = blockIdx.y * 32;
    const int tx = threadIdx.x & 31, tr = threadIdx.x >> 5;
#pragma unroll
    for (int i = tr; i < 32; i += 8) {
        int n = nb + tx;
        tile[i][tx] = (n < 2000) ? g_E[(size_t)(sb + i) * 2000 + n] : 0.f;
    }
    __syncthreads();
#pragma unroll
    for (int i = tr; i < 32; i += 8)
        g_Et[(size_t)(nb + i) * 256 + sb + tx] = tile[tx][i];
}

// ================= SIMT 64x64xK=256 GEMM core (macro body) =================
#define GEMM_BODY(Aexpr, Bexpr)                                                       \
    __shared__ float As[64][68];                                                      \
    __shared__ float Bs[64][68];                                                      \
    const int u = threadIdx.x;                                                        \
    const int tx = u & 15, ty = u >> 4;                                               \
    float acc[4][4];                                                                  \
    _Pragma("unroll") for (int i = 0; i < 4; i++)                                     \
        _Pragma("unroll") for (int j = 0; j < 4; j++) acc[i][j] = 0.f;                \
    for (int k0 = 0; k0 < 256; k0 += 64) {                                            \
        _Pragma("unroll") for (int q = 0; q < 4; q++) {                               \
            int f = q * 256 + u;                                                      \
            int row = f >> 4, kq = (f & 15) << 2;                                     \
            *(float4*)&As[row][kq] = *(const float4*)&(Aexpr);                        \
            *(float4*)&Bs[row][kq] = *(const float4*)&(Bexpr);                        \
        }                                                                             \
        __syncthreads();                                                              \
        _Pragma("unroll") for (int k2 = 0; k2 < 64; k2++) {                           \
            float a0 = As[ty * 4 + 0][k2], a1 = As[ty * 4 + 1][k2];                   \
            float a2 = As[ty * 4 + 2][k2], a3 = As[ty * 4 + 3][k2];                   \
            float4 b = *(const float4*)&Bs[k2][tx * 4];                               \
            acc[0][0] += a0 * b.x; acc[0][1] += a0 * b.y; acc[0][2] += a0 * b.z; acc[0][3] += a0 * b.w; \
            acc[1][0] += a1 * b.x; acc[1][1] += a1 * b.y; acc[1][2] += a1 * b.z; acc[1][3] += a1 * b.w; \
            acc[2][0] += a2 * b.x; acc[2][1] += a2 * b.y; acc[2][2] += a2 * b.z; acc[2][3] += a2 * b.w; \
            acc[3][0] += a3 * b.x; acc[3][1] += a3 * b.y; acc[3][2] += a3 * b.z; acc[3][3] += a3 * b.w; \
        }                                                                             \
        __syncthreads();                                                              \
    }

// Batched power: Ppow[dst+z] = Ppow[src+z] @ Ppow[pw]; also stores transpose.
__global__ __launch_bounds__(256) void k_pmul(int dst, int src, int pw) {
    const int z = blockIdx.z;
    const float* A = g_Ppow + (size_t)(src + z) * 65536;
    const float* B = g_Ppow + (size_t)pw * 65536;
    float* Cm = g_Ppow + (size_t)(dst + z) * 65536;
    float* Ct = g_Ppt + (size_t)(dst + z) * 65536;
    const int r0 = blockIdx.y * 64, c0 = blockIdx.x * 64;
    GEMM_BODY(A[(size_t)(r0 + row) * 256 + k0 + kq],
              B[(size_t)(k0 + row) * 256 + c0 + kq])
#pragma unroll
    for (int i = 0; i < 4; i++) {
        *(float4*)&Cm[(size_t)(r0 + ty * 4 + i) * 256 + c0 + tx * 4] =
            make_float4(acc[i][0], acc[i][1], acc[i][2], acc[i][3]);
#pragma unroll
        for (int j = 0; j < 4; j++)
            Ct[(size_t)(c0 + tx * 4 + j) * 256 + r0 + ty * 4 + i] = acc[i][j];
    }
}

__device__ __forceinline__ const float* Qptr(int k) {
    return (k == 1) ? (g_Ppow + (size_t)63 * 65536) : (g_Q + (size_t)k * 65536);
}

// Batched Q powers: Q^(dst0+z) = Q^(src0+z) @ Q^pw  (fp32)
__global__ __launch_bounds__(256) void k_qmul(int dst0, int src0, int pw) {
    const int z = blockIdx.z;
    const float* A = Qptr(src0 + z);
    const float* B = Qptr(pw);
    float* Cm = g_Q + (size_t)(dst0 + z) * 65536;
    const int r0 = blockIdx.y * 64, c0 = blockIdx.x * 64;
    GEMM_BODY(A[(size_t)(r0 + row) * 256 + k0 + kq],
              B[(size_t)(k0 + row) * 256 + c0 + kq])
#pragma unroll
    for (int i = 0; i < 4; i++)
        *(float4*)&Cm[(size_t)(r0 + ty * 4 + i) * 256 + c0 + tx * 4] =
            make_float4(acc[i][0], acc[i][1], acc[i][2], acc[i][3]);
}

// Backbones p[64k] = p0 @ Q^k (y=0..6), plus wp[0,:] (y=7, x=0).
__global__ __launch_bounds__(256) void k_bb_all() {
    const int k = blockIdx.y + 1;
    if (k == 8) {
        if (blockIdx.x != 0) return;
        int s = threadIdx.x;
        float a = 0.f;
#pragma unroll 8
        for (int c = 0; c < 64; c++) a += g_w[c] * g_p[c * 256 + s];
        g_wp[s] = a;
        return;
    }
    const float* A = g_p;
    const float* B = Qptr(k);
    float* Cm = g_p + (size_t)(64 * k) * 16384;
    const int c0 = blockIdx.x * 64;
    GEMM_BODY(A[(size_t)row * 256 + k0 + kq],
              B[(size_t)(k0 + row) * 256 + c0 + kq])
#pragma unroll
    for (int i = 0; i < 4; i++)
        *(float4*)&Cm[(size_t)(ty * 4 + i) * 256 + c0 + tx * 4] =
            make_float4(acc[i][0], acc[i][1], acc[i][2], acc[i][3]);
}

// ================= tf32 mma.sync =================
__device__ __forceinline__ void mma_tf32(float* c, const uint32_t* a, const uint32_t* b) {
    asm volatile(
        "mma.sync.aligned.m16n8k8.row.col.f32.tf32.tf32.f32 "
        "{%0,%1,%2,%3}, {%4,%5,%6,%7}, {%8,%9}, {%0,%1,%2,%3};"
        : "+f"(c[0]), "+f"(c[1]), "+f"(c[2]), "+f"(c[3])
        : "r"(a[0]), "r"(a[1]), "r"(a[2]), "r"(a[3]), "r"(b[0]), "r"(b[1]));
}

// Fill via MMA: p_t = p_base @ P^i, hid = log(p_t), and wp[t, c0:c0+128] epilogue.
// grid: (2 N-tiles, 499 t), 256 threads = 8 warps (2 M x 4 N)
__global__ __launch_bounds__(256) void k_fill_mma(float* __restrict__ hid) {
    __shared__ float sA[64][36];
    __shared__ float sB[128][36];
    __shared__ float sw[64];
    const int u = threadIdx.x;
    const int lane = u & 31;
    const int w = u >> 5;
    const int wm = w & 1;
    const int wn = w >> 1;
    const int t = blockIdx.y + 1;
    const int base = ((t - 1) >> 6) << 6;
    const int i = t - base;
    const float* A = g_p + (size_t)base * 16384;
    const float* Bt = g_Ppt + (size_t)(i - 1) * 65536;
    const int c0 = blockIdx.x * 128;

    if (u < 64) sw[u] = g_w[t * 64 + u];

    float acc[2][4][4];
#pragma unroll
    for (int mt = 0; mt < 2; mt++)
#pragma unroll
        for (int nt = 0; nt < 4; nt++)
#pragma unroll
            for (int r = 0; r < 4; r++) acc[mt][nt][r] = 0.f;

    const int lr = lane >> 2;
    const int lc = lane & 3;

    for (int ch = 0; ch < 8; ch++) {
        const int k0 = ch * 32;
#pragma unroll
        for (int q = 0; q < 2; q++) {
            int f = q * 256 + u;
            int row = f >> 3, c4 = (f & 7) << 2;
            *(float4*)&sA[row][c4] = *(const float4*)&A[(size_t)row * 256 + k0 + c4];
        }
#pragma unroll
        for (int q = 0; q < 4; q++) {
            int f = q * 256 + u;
            int row = f >> 3, c4 = (f & 7) << 2;
            *(float4*)&sB[row][c4] = *(const float4*)&Bt[(size_t)(c0 + row) * 256 + k0 + c4];
        }
        __syncthreads();
#pragma unroll
        for (int k8 = 0; k8 < 4; k8++) {
            const int kb = k8 * 8;
            uint32_t bfr[4][2];
#pragma unroll
            for (int nt = 0; nt < 4; nt++) {
                const int nrow = wn * 32 + nt * 8 + lr;
                bfr[nt][0] = __float_as_uint(sB[nrow][kb + lc]);
                bfr[nt][1] = __float_as_uint(sB[nrow][kb + lc + 4]);
            }
#pragma unroll
            for (int mt = 0; mt < 2; mt++) {
                const int arow = wm * 32 + mt * 16 + lr;
                uint32_t afr[4];
                afr[0] = __float_as_uint(sA[arow][kb + lc]);
                afr[1] = __float_as_uint(sA[arow + 8][kb + lc]);
                afr[2] = __float_as_uint(sA[arow][kb + lc + 4]);
                afr[3] = __float_as_uint(sA[arow + 8][kb + lc + 4]);
#pragma unroll
                for (int nt = 0; nt < 4; nt++) mma_tf32(acc[mt][nt], afr, bfr[nt]);
            }
        }
        __syncthreads();
    }

    float* pout = g_p + (size_t)t * 16384;
    float* hout = hid + (size_t)t * 16384;
#pragma unroll
    for (int mt = 0; mt < 2; mt++) {
        const int row = wm * 32 + mt * 16 + lr;
#pragma unroll
        for (int nt = 0; nt < 4; nt++) {
            const int col = c0 + wn * 32 + nt * 8 + 2 * lc;
            float2 v0 = make_float2(acc[mt][nt][0], acc[mt][nt][1]);
            float2 v1 = make_float2(acc[mt][nt][2], acc[mt][nt][3]);
            *(float2*)&pout[(size_t)row * 256 + col] = v0;
            *(float2*)&pout[(size_t)(row + 8) * 256 + col] = v1;
            *(float2*)&hout[(size_t)row * 256 + col] = make_float2(__logf(v0.x), __logf(v0.y));
            *(float2*)&hout[(size_t)(row + 8) * 256 + col] = make_float2(__logf(v1.x), __logf(v1.y));
        }
    }

    // wp epilogue: wp[t, c0+colL] = sum over 64 rows of w[t,row]*p
    float* red = &sB[0][0];  // 16 x 128 partials
    const int g = wm * 8 + lr;
    float w0 = sw[wm * 32 + lr], w0b = sw[wm * 32 + lr + 8];
    float w1 = sw[wm * 32 + 16 + lr], w1b = sw[wm * 32 + 16 + lr + 8];
#pragma unroll
    for (int nt = 0; nt < 4; nt++) {
        const int colL = wn * 32 + nt * 8 + 2 * lc;
#pragma unroll
        for (int d = 0; d < 2; d++) {
            float part = w0 * acc[0][nt][d] + w0b * acc[0][nt][d + 2] +
                         w1 * acc[1][nt][d] + w1b * acc[1][nt][d + 2];
            red[g * 128 + colL + d] = part;
        }
    }
    __syncthreads();
#pragma unroll
    for (int h = 8; h > 0; h >>= 1) {
        for (int e = u; e < h * 128; e += 256) red[e] += red[e + h * 128];
        __syncthreads();
    }
    if (u < 128) g_wp[(size_t)t * 256 + c0 + u] = red[u];
}

// ================= emission GEMM + obs (fused) =================
// y < 250: emission tile [128 rows x 128 n]; y in [250,266): obs blocks.
__global__ __launch_bounds__(256) void k_emis_obs(float* __restrict__ out) {
    __shared__ float pool[2 * 128 * 36 + 128];
    const int u = threadIdx.x;

    if (blockIdx.y >= 250) {
        // ---- obs role: 256 blocks, each 16 t's x 256 n's ----
        float* wsm = pool;  // 16*256 = 4096 floats
        const int idx = (blockIdx.y - 250) * 16 + blockIdx.x;
        const int t0 = (idx >> 3) * 16;
        const int n = (idx & 7) * 256 + u;
#pragma unroll
        for (int j = 0; j < 16; j++)
            wsm[j * 256 + u] = (t0 + j < 500) ? g_wp[(size_t)(t0 + j) * 256 + u] : 0.f;
        __syncthreads();
        float acc[16];
#pragma unroll
        for (int j = 0; j < 16; j++) acc[j] = 0.f;
        for (int s = 0; s < 256; s++) {
            float e = (n < 2000) ? g_E[(size_t)s * 2000 + n] : 0.f;
#pragma unroll
            for (int j = 0; j < 16; j++) acc[j] += wsm[j * 256 + s] * e;
        }
        if (n < 2000) {
            float bm = g_bmaxE[n];
#pragma unroll
            for (int j = 0; j < 16; j++)
                if (t0 + j < 500) out[(size_t)(t0 + j) * 2000 + n] = __logf(acc[j]) + bm;
        }
        return;
    }

    // ---- emission role (R4 proven mainloop) ----
    float (*sA)[36] = (float(*)[36])pool;
    float (*sB)[36] = (float(*)[36])(pool + 128 * 36);
    float* sBM = pool + 2 * 128 * 36;

    const int lane = u & 31;
    const int w = u >> 5;
    const int wm = w & 3;
    const int wn = w >> 2;
    const int n0 = blockIdx.x * 128;
    const int r0 = blockIdx.y * 128;

    if (u < 128) sBM[u] = g_bmaxE[n0 + u];

    float acc[2][8][4];
#pragma unroll
    for (int mt = 0; mt < 2; mt++)
#pragma unroll
        for (int nt = 0; nt < 8; nt++)
#pragma unroll
            for (int r = 0; r < 4; r++) acc[mt][nt][r] = 0.f;

    const int lr = lane >> 2;
    const int lc = lane & 3;

    for (int ch = 0; ch < 8; ch++) {
        const int k0 = ch * 32;
#pragma unroll
        for (int q = 0; q < 4; q++) {
            int f = q * 256 + u;
            int row = f >> 3, c4 = (f & 7) << 2;
            *(float4*)&sA[row][c4] = *(const float4*)&g_p[(size_t)(r0 + row) * 256 + k0 + c4];
            *(float4*)&sB[row][c4] = *(const float4*)&g_Et[(size_t)(n0 + row) * 256 + k0 + c4];
        }
        __syncthreads();
#pragma unroll
        for (int k8 = 0; k8 < 4; k8++) {
            const int kb = k8 * 8;
            uint32_t bfr[8][2];
#pragma unroll
            for (int nt = 0; nt < 8; nt++) {
                const int nrow = wn * 64 + nt * 8 + lr;
                bfr[nt][0] = __float_as_uint(sB[nrow][kb + lc]);
                bfr[nt][1] = __float_as_uint(sB[nrow][kb + lc + 4]);
            }
#pragma unroll
            for (int mt = 0; mt < 2; mt++) {
                const int arow = wm * 32 + mt * 16 + lr;
                uint32_t afr[4];
                afr[0] = __float_as_uint(sA[arow][kb + lc]);
                afr[1] = __float_as_uint(sA[arow + 8][kb + lc]);
                afr[2] = __float_as_uint(sA[arow][kb + lc + 4]);
                afr[3] = __float_as_uint(sA[arow + 8][kb + lc + 4]);
#pragma unroll
                for (int nt = 0; nt < 8; nt++) mma_tf32(acc[mt][nt], afr, bfr[nt]);
            }
        }
        __syncthreads();
    }

    float* obsp = out + 1000000u;
#pragma unroll
    for (int mt = 0; mt < 2; mt++) {
        const int row = r0 + wm * 32 + mt * 16 + lr;
#pragma unroll
        for (int nt = 0; nt < 8; nt++) {
            const int col = wn * 64 + nt * 8 + 2 * lc;
            const int n = n0 + col;
            if (n < 2000) {
                float2 v0, v1;
                v0.x = __logf(acc[mt][nt][0]) + sBM[col];
                v0.y = __logf(acc[mt][nt][1]) + sBM[col + 1];
                v1.x = __logf(acc[mt][nt][2]) + sBM[col];
                v1.y = __logf(acc[mt][nt][3]) + sBM[col + 1];
                *(float2*)&obsp[(size_t)row * 2000 + n] = v0;
                *(float2*)&obsp[(size_t)(row + 8) * 2000 + n] = v1;
            }
        }
    }
}

// ================= launch =================
extern "C" void kernel_launch(void* const* d_in, const int* in_sizes, int n_in,
                              void* d_out, int out_size) {
    const float* usi = (const float*)d_in[0];  // [64,256]
    const float* ucw = (const float*)d_in[1];  // [500,64]
    const float* uem = (const float*)d_in[2];  // [256,2000]
    const float* utm = (const float*)d_in[3];  // [256,256]
    const float* msk = (const float*)d_in[4];  // [256,2000]
    float* out = (float*)d_out;
    float* hid = out + 65000000u;

    k_pre<<<383, 256>>>(usi, ucw, utm, hid);
    k_Erow<<<256, 256>>>(uem, msk);
    k_Ecol<<<8, 256>>>();
    k_transposeE<<<dim3(63, 8), 256>>>();

    // P^1..P^64 by batched doubling (fp32, also stores transposes)
    k_pmul<<<dim3(4, 4, 1), 256>>>(1, 0, 0);
    k_pmul<<<dim3(4, 4, 2), 256>>>(2, 0, 1);
    k_pmul<<<dim3(4, 4, 4), 256>>>(4, 0, 3);
    k_pmul<<<dim3(4, 4, 8), 256>>>(8, 0, 7);
    k_pmul<<<dim3(4, 4, 16), 256>>>(16, 0, 15);
    k_pmul<<<dim3(4, 4, 32), 256>>>(32, 0, 31);

    // Q = P^64; Q^2..Q^7 via batched doubling (fp32)
    k_qmul<<<dim3(4, 4, 1), 256>>>(2, 1, 1);
    k_qmul<<<dim3(4, 4, 2), 256>>>(3, 1, 2);
    k_qmul<<<dim3(4, 4, 3), 256>>>(5, 1, 4);

    // backbones + wp[0,:]
    k_bb_all<<<dim3(4, 8), 256>>>();

    // all t = 1..499 via tf32 MMA (writes p, log_hidden, and wp)
    k_fill_mma<<<dim3(2, 499), 256>>>(hid);

    // emission + obs fused
    k_emis_obs<<<dim3(16, 266), 256>>>(out);
}